// round 3
// baseline (speedup 1.0000x reference)
#include <cuda_runtime.h>
#include <cuda_bf16.h>

#define FEAT      4096
#define NTHREADS  512
#define PER       8           // FEAT / NTHREADS
#define SEL_RANK  2048u       // 0-indexed rank of smallest KEPT element
#define SCALE     2.0f        // FEAT / NACTIVE

// monotone fp32 -> u32 key (ascending float order == ascending uint order)
__device__ __forceinline__ unsigned int fkey(float f) {
    unsigned int u = __float_as_uint(f);
    return u ^ ((unsigned int)((int)u >> 31) | 0x80000000u);
}
// inverse key -> fp32 (branchless)
__device__ __forceinline__ float kinv(unsigned int k) {
    unsigned int m = (unsigned int)((int)(~k) >> 31) | 0x80000000u;
    return __uint_as_float(k ^ m);
}

__global__ __launch_bounds__(NTHREADS)
void MaxoutDynamic_kernel(const float* __restrict__ feat, float* __restrict__ out) {
    __shared__ __align__(16) unsigned int hist[4096];   // 16 KB
    __shared__ unsigned int wsum[16];
    __shared__ unsigned int s_pr[2];   // {prefix, rank}

    const int tid = threadIdx.x;
    const unsigned int lane = tid & 31;
    const unsigned int wid  = tid >> 5;
    const size_t row_off = (size_t)blockIdx.x * FEAT;

    // ---- load row (2 x float4 per thread), zero histogram while loads fly ----
    const float4* in4 = reinterpret_cast<const float4*>(feat + row_off);
    float4 va = in4[tid];
    float4 vb = in4[tid + NTHREADS];

    uint4* h4 = reinterpret_cast<uint4*>(hist);
    const uint4 z4 = make_uint4(0u, 0u, 0u, 0u);
    h4[tid]            = z4;
    h4[tid + NTHREADS] = z4;

    unsigned int key[PER];
    key[0] = fkey(va.x); key[1] = fkey(va.y); key[2] = fkey(va.z); key[3] = fkey(va.w);
    key[4] = fkey(vb.x); key[5] = fkey(vb.y); key[6] = fkey(vb.z); key[7] = fkey(vb.w);
    __syncthreads();

    // ---- pass 0: unpredicated histogram of ALL elements, bits 31:20 (4096 bins) ----
    #pragma unroll
    for (int e = 0; e < PER; e++)
        atomicAdd(&hist[key[e] >> 20], 1u);
    __syncthreads();

    // read own 8 bins + re-zero in place (pass 1 reuses bins 0..1023)
    uint4 a0 = h4[2 * tid];
    uint4 a1 = h4[2 * tid + 1];
    h4[2 * tid]     = z4;
    h4[2 * tid + 1] = z4;
    unsigned int c[8] = {a0.x, a0.y, a0.z, a0.w, a1.x, a1.y, a1.z, a1.w};
    unsigned int csum = c[0] + c[1] + c[2] + c[3] + c[4] + c[5] + c[6] + c[7];

    // warp inclusive scan of chunk sums
    unsigned int v = csum;
    #pragma unroll
    for (int off = 1; off < 32; off <<= 1) {
        unsigned int t = __shfl_up_sync(0xFFFFFFFFu, v, off);
        if (lane >= (unsigned)off) v += t;
    }
    if (lane == 31) wsum[wid] = v;
    __syncthreads();

    unsigned int wb = 0;
    #pragma unroll
    for (int w = 0; w < 15; w++) if (w < (int)wid) wb += wsum[w];
    unsigned int base_excl = wb + (v - csum);

    // locate the bin containing global rank SEL_RANK
    if (SEL_RANK - base_excl < csum) {
        unsigned int r = SEL_RANK - base_excl;
        unsigned int d = 0;
        #pragma unroll
        for (int i = 0; i < 8; i++) {
            if (r < c[i]) { d = (unsigned int)(tid * 8 + i); break; }
            r -= c[i];
        }
        s_pr[0] = d << 20;
        s_pr[1] = r;
    }
    __syncthreads();

    unsigned int prefix = s_pr[0];
    unsigned int rank   = s_pr[1];

    // ---- pass 1: bits 19:10 (1024 bins) of candidates matching 12-bit prefix ----
    #pragma unroll
    for (int e = 0; e < PER; e++) {
        unsigned int k = key[e];
        if ((k & 0xFFF00000u) == prefix)
            atomicAdd(&hist[(k >> 10) & 1023u], 1u);
    }
    __syncthreads();

    // scan 1024 bins, 2 per thread
    uint2 cc = reinterpret_cast<uint2*>(hist)[tid];
    csum = cc.x + cc.y;
    v = csum;
    #pragma unroll
    for (int off = 1; off < 32; off <<= 1) {
        unsigned int t = __shfl_up_sync(0xFFFFFFFFu, v, off);
        if (lane >= (unsigned)off) v += t;
    }
    if (lane == 31) wsum[wid] = v;
    __syncthreads();

    wb = 0;
    #pragma unroll
    for (int w = 0; w < 15; w++) if (w < (int)wid) wb += wsum[w];
    base_excl = wb + (v - csum);

    if (rank - base_excl < csum) {
        unsigned int r = rank - base_excl;
        unsigned int d = (r < cc.x) ? (unsigned int)(2 * tid) : (unsigned int)(2 * tid + 1);
        s_pr[0] = prefix | (d << 10);
    }
    __syncthreads();

    const unsigned int K = s_pr[0];   // 22-bit threshold key (bits 9:0 zero)

    // ---- predicated scaled writeback ----
    float4* out4 = reinterpret_cast<float4*>(out + row_off);
    float4 r0, r1;
    r0.x = (key[0] >= K) ? SCALE * kinv(key[0]) : 0.0f;
    r0.y = (key[1] >= K) ? SCALE * kinv(key[1]) : 0.0f;
    r0.z = (key[2] >= K) ? SCALE * kinv(key[2]) : 0.0f;
    r0.w = (key[3] >= K) ? SCALE * kinv(key[3]) : 0.0f;
    r1.x = (key[4] >= K) ? SCALE * kinv(key[4]) : 0.0f;
    r1.y = (key[5] >= K) ? SCALE * kinv(key[5]) : 0.0f;
    r1.z = (key[6] >= K) ? SCALE * kinv(key[6]) : 0.0f;
    r1.w = (key[7] >= K) ? SCALE * kinv(key[7]) : 0.0f;
    out4[tid]            = r0;
    out4[tid + NTHREADS] = r1;
}

extern "C" void kernel_launch(void* const* d_in, const int* in_sizes, int n_in,
                              void* d_out, int out_size) {
    const float* feat = (const float*)d_in[0];
    float* out = (float*)d_out;
    const int rows = in_sizes[0] / FEAT;   // 16384
    MaxoutDynamic_kernel<<<rows, NTHREADS>>>(feat, out);
}

// round 4
// speedup vs baseline: 1.2002x; 1.2002x over previous
#include <cuda_runtime.h>
#include <cuda_bf16.h>

#define FEAT      4096
#define NTHREADS  512
#define PER       8           // FEAT / NTHREADS
#define SEL_RANK  2048u       // 0-indexed rank of smallest KEPT element
#define SCALE     2.0f        // FEAT / NACTIVE
#define CAND_MAX  1024

// monotone fp32 -> u32 key (ascending float order == ascending uint order)
__device__ __forceinline__ unsigned int fkey(float f) {
    unsigned int u = __float_as_uint(f);
    return u ^ ((unsigned int)((int)u >> 31) | 0x80000000u);
}
// inverse key -> fp32 (branchless)
__device__ __forceinline__ float kinv(unsigned int k) {
    unsigned int m = (unsigned int)((int)(~k) >> 31) | 0x80000000u;
    return __uint_as_float(k ^ m);
}

__global__ __launch_bounds__(NTHREADS)
void MaxoutDynamic_kernel(const float* __restrict__ feat, float* __restrict__ out) {
    __shared__ __align__(16) unsigned int hist[4096];   // 16 KB, bits 31:20
    __shared__ __align__(16) unsigned int cand[CAND_MAX];
    __shared__ unsigned int wsum[16];
    __shared__ unsigned int s_bin, s_rank, s_key, s_cnt;

    const int tid = threadIdx.x;
    const unsigned int lane = tid & 31;
    const unsigned int wid  = tid >> 5;
    const size_t row_off = (size_t)blockIdx.x * FEAT;

    // ---- load row (2 x float4), zero histogram while loads are in flight ----
    const float4* in4 = reinterpret_cast<const float4*>(feat + row_off);
    float4 va = in4[tid];
    float4 vb = in4[tid + NTHREADS];

    uint4* h4 = reinterpret_cast<uint4*>(hist);
    const uint4 z4 = make_uint4(0u, 0u, 0u, 0u);
    h4[tid]            = z4;
    h4[tid + NTHREADS] = z4;
    if (tid == 0) s_cnt = 0u;

    unsigned int key[PER];
    key[0] = fkey(va.x); key[1] = fkey(va.y); key[2] = fkey(va.z); key[3] = fkey(va.w);
    key[4] = fkey(vb.x); key[5] = fkey(vb.y); key[6] = fkey(vb.z); key[7] = fkey(vb.w);
    __syncthreads();

    // ---- pass 0: unpredicated 4096-bin histogram of top 12 key bits ----
    #pragma unroll
    for (int e = 0; e < PER; e++)
        atomicAdd(&hist[key[e] >> 20], 1u);
    __syncthreads();

    // each thread owns 8 consecutive bins
    uint4 a0 = h4[2 * tid];
    uint4 a1 = h4[2 * tid + 1];
    unsigned int c[8] = {a0.x, a0.y, a0.z, a0.w, a1.x, a1.y, a1.z, a1.w};
    const unsigned int csum = c[0] + c[1] + c[2] + c[3] + c[4] + c[5] + c[6] + c[7];

    // warp inclusive scan of chunk sums
    unsigned int v = csum;
    #pragma unroll
    for (int off = 1; off < 32; off <<= 1) {
        unsigned int t = __shfl_up_sync(0xFFFFFFFFu, v, off);
        if (lane >= (unsigned)off) v += t;
    }
    if (lane == 31) wsum[wid] = v;
    __syncthreads();

    // warp 0 turns wsum into exclusive warp bases
    if (tid < 32) {
        unsigned int w = (tid < 16) ? wsum[tid] : 0u;
        unsigned int wi = w;
        #pragma unroll
        for (int off = 1; off < 16; off <<= 1) {
            unsigned int t = __shfl_up_sync(0xFFFFFFFFu, wi, off);
            if (lane >= (unsigned)off) wi += t;
        }
        if (tid < 16) wsum[tid] = wi - w;   // exclusive
    }
    __syncthreads();

    // locate the bin containing global rank SEL_RANK
    const unsigned int base_excl = wsum[wid] + (v - csum);
    if (SEL_RANK - base_excl < csum) {   // unsigned in-range trick
        unsigned int r = SEL_RANK - base_excl;
        unsigned int d = 0;
        #pragma unroll
        for (int i = 0; i < 8; i++) {
            if (r < c[i]) { d = (unsigned int)(tid * 8 + i); break; }
            r -= c[i];
        }
        s_bin  = d;
        s_rank = r;
    }
    __syncthreads();

    const unsigned int bin = s_bin;

    // ---- append candidates in the selected bin (typically only ~4-16 total) ----
    #pragma unroll
    for (int e = 0; e < PER; e++) {
        if ((key[e] >> 20) == bin) {
            unsigned int idx = atomicAdd(&s_cnt, 1u);
            if (idx < CAND_MAX) cand[idx] = key[e];
        }
    }
    __syncthreads();

    // ---- warp 0: exact rank-r selection among n candidates (stable) ----
    if (wid == 0) {
        unsigned int n = s_cnt;
        if (n > CAND_MAX) n = CAND_MAX;
        const unsigned int r = s_rank;
        for (unsigned int i = lane; i < n; i += 32) {
            unsigned int k = cand[i];
            unsigned int cnt = 0;
            for (unsigned int j = 0; j < n; j++) {
                unsigned int kj = cand[j];
                cnt += (kj < k) || (kj == k && j < i);
            }
            if (cnt == r) s_key = k;   // exactly one winner
        }
    }
    __syncthreads();

    const unsigned int K = s_key;   // exact 32-bit threshold key

    // ---- predicated scaled writeback ----
    float4* out4 = reinterpret_cast<float4*>(out + row_off);
    float4 r0, r1;
    r0.x = (key[0] >= K) ? SCALE * kinv(key[0]) : 0.0f;
    r0.y = (key[1] >= K) ? SCALE * kinv(key[1]) : 0.0f;
    r0.z = (key[2] >= K) ? SCALE * kinv(key[2]) : 0.0f;
    r0.w = (key[3] >= K) ? SCALE * kinv(key[3]) : 0.0f;
    r1.x = (key[4] >= K) ? SCALE * kinv(key[4]) : 0.0f;
    r1.y = (key[5] >= K) ? SCALE * kinv(key[5]) : 0.0f;
    r1.z = (key[6] >= K) ? SCALE * kinv(key[6]) : 0.0f;
    r1.w = (key[7] >= K) ? SCALE * kinv(key[7]) : 0.0f;
    out4[tid]            = r0;
    out4[tid + NTHREADS] = r1;
}

extern "C" void kernel_launch(void* const* d_in, const int* in_sizes, int n_in,
                              void* d_out, int out_size) {
    const float* feat = (const float*)d_in[0];
    float* out = (float*)d_out;
    const int rows = in_sizes[0] / FEAT;   // 16384
    MaxoutDynamic_kernel<<<rows, NTHREADS>>>(feat, out);
}

// round 5
// speedup vs baseline: 1.3479x; 1.1231x over previous
#include <cuda_runtime.h>
#include <cuda_bf16.h>

#define FEAT      4096
#define NTHREADS  512
#define PER       8           // FEAT / NTHREADS
#define SEL_RANK  2048u       // 0-indexed rank of smallest KEPT element
#define SCALE     2.0f        // FEAT / NACTIVE
#define CAND_MAX  256

// monotone fp32 -> u32 key (ascending float order == ascending uint order)
__device__ __forceinline__ unsigned int fkey(float f) {
    unsigned int u = __float_as_uint(f);
    return u ^ ((unsigned int)((int)u >> 31) | 0x80000000u);
}
// inverse key -> fp32 (branchless)
__device__ __forceinline__ float kinv(unsigned int k) {
    unsigned int m = (unsigned int)((int)(~k) >> 31) | 0x80000000u;
    return __uint_as_float(k ^ m);
}

__global__ __launch_bounds__(NTHREADS, 4)
void MaxoutDynamic_kernel(const float* __restrict__ feat, float* __restrict__ out) {
    __shared__ __align__(16) unsigned int hist[4096];   // 16 KB, bits 31:20
    __shared__ __align__(16) unsigned int cand[CAND_MAX];
    __shared__ unsigned int wsum[16];
    __shared__ unsigned int s_bin, s_rank, s_key, s_cnt;

    const int tid = threadIdx.x;
    const unsigned int lane = tid & 31;
    const unsigned int wid  = tid >> 5;
    const size_t row_off = (size_t)blockIdx.x * FEAT;

    // ---- load row (2 x float4), zero histogram while loads are in flight ----
    const float4* in4 = reinterpret_cast<const float4*>(feat + row_off);
    float4 va = in4[tid];
    float4 vb = in4[tid + NTHREADS];

    uint4* h4 = reinterpret_cast<uint4*>(hist);
    const uint4 z4 = make_uint4(0u, 0u, 0u, 0u);
    h4[tid]            = z4;
    h4[tid + NTHREADS] = z4;
    if (tid == 0) s_cnt = 0u;

    unsigned int key[PER];
    key[0] = fkey(va.x); key[1] = fkey(va.y); key[2] = fkey(va.z); key[3] = fkey(va.w);
    key[4] = fkey(vb.x); key[5] = fkey(vb.y); key[6] = fkey(vb.z); key[7] = fkey(vb.w);
    __syncthreads();

    // ---- pass 0: unpredicated 4096-bin histogram of top 12 key bits ----
    #pragma unroll
    for (int e = 0; e < PER; e++)
        atomicAdd(&hist[key[e] >> 20], 1u);
    __syncthreads();

    // each thread owns 8 consecutive bins
    uint4 a0 = h4[2 * tid];
    uint4 a1 = h4[2 * tid + 1];
    unsigned int c[8] = {a0.x, a0.y, a0.z, a0.w, a1.x, a1.y, a1.z, a1.w};
    const unsigned int csum = c[0] + c[1] + c[2] + c[3] + c[4] + c[5] + c[6] + c[7];

    // warp inclusive scan of chunk sums
    unsigned int v = csum;
    #pragma unroll
    for (int off = 1; off < 32; off <<= 1) {
        unsigned int t = __shfl_up_sync(0xFFFFFFFFu, v, off);
        if (lane >= (unsigned)off) v += t;
    }
    if (lane == 31) wsum[wid] = v;
    __syncthreads();

    // every warp redundantly scans the 16 warp totals (no extra barrier)
    unsigned int w  = (lane < 16u) ? wsum[lane] : 0u;
    unsigned int wi = w;
    #pragma unroll
    for (int off = 1; off < 16; off <<= 1) {
        unsigned int t = __shfl_up_sync(0xFFFFFFFFu, wi, off);
        if (lane >= (unsigned)off) wi += t;
    }
    const unsigned int warp_base = __shfl_sync(0xFFFFFFFFu, wi - w, wid);

    // locate the bin containing global rank SEL_RANK
    const unsigned int base_excl = warp_base + (v - csum);
    if (SEL_RANK - base_excl < csum) {   // unsigned in-range trick
        unsigned int r = SEL_RANK - base_excl;
        unsigned int d = 0;
        #pragma unroll
        for (int i = 0; i < 8; i++) {
            if (r < c[i]) { d = (unsigned int)(tid * 8 + i); break; }
            r -= c[i];
        }
        s_bin  = d;
        s_rank = r;
    }
    __syncthreads();

    const unsigned int bin = s_bin;

    // ---- append candidates in the selected bin (typically ~4-25 total) ----
    #pragma unroll
    for (int e = 0; e < PER; e++) {
        if ((key[e] >> 20) == bin) {
            unsigned int idx = atomicAdd(&s_cnt, 1u);
            if (idx < CAND_MAX) cand[idx] = key[e];
        }
    }
    __syncthreads();

    // ---- warp 0: exact rank-r selection among n candidates (stable) ----
    if (wid == 0) {
        unsigned int n = s_cnt;
        if (n > CAND_MAX) n = CAND_MAX;
        const unsigned int r = s_rank;
        for (unsigned int i = lane; i < n; i += 32) {
            unsigned int k = cand[i];
            unsigned int cnt = 0;
            for (unsigned int j = 0; j < n; j++) {
                unsigned int kj = cand[j];
                cnt += (kj < k) || (kj == k && j < i);
            }
            if (cnt == r) s_key = k;   // exactly one winner
        }
    }
    __syncthreads();

    const unsigned int K = s_key;   // exact 32-bit threshold key

    // ---- predicated scaled writeback ----
    float4* out4 = reinterpret_cast<float4*>(out + row_off);
    float4 r0, r1;
    r0.x = (key[0] >= K) ? SCALE * kinv(key[0]) : 0.0f;
    r0.y = (key[1] >= K) ? SCALE * kinv(key[1]) : 0.0f;
    r0.z = (key[2] >= K) ? SCALE * kinv(key[2]) : 0.0f;
    r0.w = (key[3] >= K) ? SCALE * kinv(key[3]) : 0.0f;
    r1.x = (key[4] >= K) ? SCALE * kinv(key[4]) : 0.0f;
    r1.y = (key[5] >= K) ? SCALE * kinv(key[5]) : 0.0f;
    r1.z = (key[6] >= K) ? SCALE * kinv(key[6]) : 0.0f;
    r1.w = (key[7] >= K) ? SCALE * kinv(key[7]) : 0.0f;
    out4[tid]            = r0;
    out4[tid + NTHREADS] = r1;
}

extern "C" void kernel_launch(void* const* d_in, const int* in_sizes, int n_in,
                              void* d_out, int out_size) {
    const float* feat = (const float*)d_in[0];
    float* out = (float*)d_out;
    const int rows = in_sizes[0] / FEAT;   // 16384
    MaxoutDynamic_kernel<<<rows, NTHREADS>>>(feat, out);
}